// round 14
// baseline (speedup 1.0000x reference)
#include <cuda_runtime.h>
#include <math.h>

#define L_SEQ   2048
#define EMB     1024
#define NHEAD   16
#define HD      64
#define BATCH   2
#define M_ROWS  (BATCH * L_SEQ)   /* 4096 */
#define QKV_N   (3 * EMB)         /* 3072 */

#define BQ 64
#define BK 32

// ---------------- Scratch (allocation-free) ----------------
__device__ float g_qkv[(size_t)M_ROWS * QKV_N];   // 48 MB
__device__ float g_att[(size_t)M_ROWS * EMB];     // 16 MB
__device__ float g_qn[(size_t)BATCH * NHEAD * L_SEQ];
__device__ float g_kn[(size_t)BATCH * NHEAD * L_SEQ];

// ---------------------------------------------------------------------------
// fp32 SGEMM (byte-identical to passing R4): C = A@B + bias
// 128x128 tile, K-step 8, 256 threads, 8x8 microtile, double-buffered smem.
// ---------------------------------------------------------------------------
__device__ __forceinline__ void sgemm_body(const float* __restrict__ A,
                                           const float* __restrict__ B,
                                           const float* __restrict__ bias,
                                           float* __restrict__ C,
                                           int M, int N, int K)
{
    __shared__ __align__(16) float As[2][8][132];
    __shared__ __align__(16) float Bs[2][8][132];

    const int tid = threadIdx.x;
    const int bm = blockIdx.y * 128;
    const int bn = blockIdx.x * 128;

    const int tx = tid % 16;
    const int ty = tid / 16;

    const int arow  = tid >> 1;
    const int acol4 = (tid & 1) * 4;
    const int brow = tid >> 5;
    const int bcol = (tid & 31) * 4;

    float acc[8][8];
#pragma unroll
    for (int i = 0; i < 8; i++)
#pragma unroll
        for (int j = 0; j < 8; j++) acc[i][j] = 0.f;

    float4 a4 = *(const float4*)(A + (size_t)(bm + arow) * K + acol4);
    float4 b4 = *(const float4*)(B + (size_t)brow * N + bn + bcol);
    As[0][acol4 + 0][arow] = a4.x;
    As[0][acol4 + 1][arow] = a4.y;
    As[0][acol4 + 2][arow] = a4.z;
    As[0][acol4 + 3][arow] = a4.w;
    *(float4*)&Bs[0][brow][bcol] = b4;
    __syncthreads();

    int cur = 0;
    for (int k0 = 0; k0 < K; k0 += 8) {
        const int nxt = cur ^ 1;
        const bool more = (k0 + 8 < K);
        if (more) {
            a4 = *(const float4*)(A + (size_t)(bm + arow) * K + k0 + 8 + acol4);
            b4 = *(const float4*)(B + (size_t)(k0 + 8 + brow) * N + bn + bcol);
        }

#pragma unroll
        for (int kk = 0; kk < 8; kk++) {
            float a[8], b[8];
#pragma unroll
            for (int h4 = 0; h4 < 2; h4++) {
                float4 t = *(const float4*)&As[cur][kk][ty * 8 + h4 * 4];
                a[h4*4+0]=t.x; a[h4*4+1]=t.y; a[h4*4+2]=t.z; a[h4*4+3]=t.w;
            }
#pragma unroll
            for (int h4 = 0; h4 < 2; h4++) {
                float4 t = *(const float4*)&Bs[cur][kk][tx * 8 + h4 * 4];
                b[h4*4+0]=t.x; b[h4*4+1]=t.y; b[h4*4+2]=t.z; b[h4*4+3]=t.w;
            }
#pragma unroll
            for (int i = 0; i < 8; i++)
#pragma unroll
                for (int j = 0; j < 8; j++)
                    acc[i][j] += a[i] * b[j];
        }

        if (more) {
            As[nxt][acol4 + 0][arow] = a4.x;
            As[nxt][acol4 + 1][arow] = a4.y;
            As[nxt][acol4 + 2][arow] = a4.z;
            As[nxt][acol4 + 3][arow] = a4.w;
            *(float4*)&Bs[nxt][brow][bcol] = b4;
        }
        __syncthreads();
        cur = nxt;
    }

#pragma unroll
    for (int i = 0; i < 8; i++) {
        int m = bm + ty * 8 + i;
#pragma unroll
        for (int j = 0; j < 8; j += 4) {
            int n = bn + tx * 8 + j;
            float4 r;
            r.x = acc[i][j + 0] + bias[n + 0];
            r.y = acc[i][j + 1] + bias[n + 1];
            r.z = acc[i][j + 2] + bias[n + 2];
            r.w = acc[i][j + 3] + bias[n + 3];
            *(float4*)(C + (size_t)m * N + n) = r;
        }
    }
}

__global__ __launch_bounds__(256, 2) void gemm_qkv_kernel(const float* __restrict__ x,
                                                          const float* __restrict__ w,
                                                          const float* __restrict__ bias)
{
    sgemm_body(x, w, bias, g_qkv, M_ROWS, QKV_N, EMB);
}

__global__ __launch_bounds__(256, 2) void gemm_out_kernel(const float* __restrict__ w,
                                                          const float* __restrict__ bias,
                                                          float* __restrict__ out)
{
    sgemm_body(g_att, w, bias, out, M_ROWS, EMB, EMB);
}

// ---------------- qn/kn precompute: one thread per (b,h,pos) ---------------
__global__ __launch_bounds__(256) void norm_kernel()
{
    int idx = blockIdx.x * 256 + threadIdx.x;
    if (idx >= BATCH * NHEAD * L_SEQ) return;
    int pos = idx & (L_SEQ - 1);
    int h   = (idx >> 11) & (NHEAD - 1);
    int b   = idx >> 15;
    const float* qp = g_qkv + (size_t)(b * L_SEQ + pos) * QKV_N + h * HD;
    float qs = 0.f, ks = 0.f;
#pragma unroll
    for (int d = 0; d < HD; d += 4) {
        float4 q = *(const float4*)(qp + d);
        float4 k = *(const float4*)(qp + EMB + d);
        qs += q.x*q.x + q.y*q.y + q.z*q.z + q.w*q.w;
        ks += k.x*k.x + k.y*k.y + k.z*k.z + k.w*k.w;
    }
    size_t o = ((size_t)b * NHEAD + h) * L_SEQ + pos;
    g_qn[o] = qs;
    g_kn[o] = ks;
}

// ---------------- half-warp (16-lane) shuffle reductions -------------------
__device__ __forceinline__ float hw_max(float v) {
    v = fmaxf(v, __shfl_xor_sync(0xffffffffu, v, 1));
    v = fmaxf(v, __shfl_xor_sync(0xffffffffu, v, 2));
    v = fmaxf(v, __shfl_xor_sync(0xffffffffu, v, 4));
    v = fmaxf(v, __shfl_xor_sync(0xffffffffu, v, 8));
    return v;
}
__device__ __forceinline__ float hw_sum(float v) {
    v += __shfl_xor_sync(0xffffffffu, v, 1);
    v += __shfl_xor_sync(0xffffffffu, v, 2);
    v += __shfl_xor_sync(0xffffffffu, v, 4);
    v += __shfl_xor_sync(0xffffffffu, v, 8);
    return v;
}

// ---------------------------------------------------------------------------
// Yat causal attention v3: shuffle reductions, per-thread m/l, 3 syncs/tile.
// Block 256 threads (16x16); tile BQ=64 x BK=32; thread (ty,tx) owns query
// rows i0..i0+3 (the 16 threads of a row group are contiguous half-warp lanes).
// ---------------------------------------------------------------------------
__global__ __launch_bounds__(256) void yat_attn_kernel()
{
    __shared__ __align__(16) float Qs[BQ][68];
    __shared__ __align__(16) float Ks[BK][68];
    __shared__ __align__(16) float Vs[BK][68];
    __shared__ __align__(16) float Ps[BK][68];   // P transposed: Ps[j][i]

    const int qt = blockIdx.x;
    const int h  = blockIdx.y;
    const int b  = blockIdx.z;
    const int tid = threadIdx.x;
    const int tx = tid & 15;
    const int ty = tid >> 4;
    const int i0 = ty * 4;
    const int j0 = tx * 2;
    const int d0 = tx * 4;
    const int qbase = qt * BQ;

    const float* qkv_b = g_qkv + (size_t)b * L_SEQ * QKV_N;
    const float* qnrm  = g_qn + ((size_t)b * NHEAD + h) * L_SEQ;
    const float* knrm  = g_kn + ((size_t)b * NHEAD + h) * L_SEQ;

    // Load Q tile
    for (int it = tid; it < BQ * 16; it += 256) {
        int r = it >> 4, c4 = (it & 15) * 4;
        *(float4*)&Qs[r][c4] =
            *(const float4*)(qkv_b + (size_t)(qbase + r) * QKV_N + h * HD + c4);
    }

    // Per-thread row state (redundant across the 16 threads of a row group)
    float4 qn4v = *(const float4*)(qnrm + qbase + i0);
    float qn4[4] = {qn4v.x, qn4v.y, qn4v.z, qn4v.w};
    float mreg[4] = {-1e30f, -1e30f, -1e30f, -1e30f};
    float lreg[4] = {0.f, 0.f, 0.f, 0.f};

    float o[4][4];
#pragma unroll
    for (int i = 0; i < 4; i++)
#pragma unroll
        for (int d = 0; d < 4; d++) o[i][d] = 0.f;

    const int nkt = 2 * qt + 2;
    for (int kt = 0; kt < nkt; kt++) {
        const int k0 = kt * BK;
        const bool diag = (kt >= 2 * qt);
        __syncthreads();   // prior PV / Ps reads done; Q ready (kt==0)

        // Load K,V tiles
        for (int it = tid; it < BK * 16; it += 256) {
            int r = it >> 4, c4 = (it & 15) * 4;
            const float* kp = qkv_b + (size_t)(k0 + r) * QKV_N + EMB + h * HD + c4;
            *(float4*)&Ks[r][c4] = *(const float4*)kp;
            *(float4*)&Vs[r][c4] = *(const float4*)(kp + EMB);
        }
        __syncthreads();

        // S = Q K^T, 4x2 microtile
        float s_[4][2];
#pragma unroll
        for (int i = 0; i < 4; i++) { s_[i][0] = 0.f; s_[i][1] = 0.f; }
#pragma unroll
        for (int d = 0; d < HD; d += 4) {
            float4 k0v = *(const float4*)&Ks[j0 + 0][d];
            float4 k1v = *(const float4*)&Ks[j0 + 1][d];
#pragma unroll
            for (int i = 0; i < 4; i++) {
                float4 qv = *(const float4*)&Qs[i0 + i][d];
                s_[i][0] += qv.x * k0v.x + qv.y * k0v.y + qv.z * k0v.z + qv.w * k0v.w;
                s_[i][1] += qv.x * k1v.x + qv.y * k1v.y + qv.z * k1v.z + qv.w * k1v.w;
            }
        }

        // Yat transform + causal mask
        const float kna = knrm[k0 + j0];
        const float knb = knrm[k0 + j0 + 1];
        float sc[4][2];
#pragma unroll
        for (int i = 0; i < 4; i++) {
            float dot0 = s_[i][0];
            float dot1 = s_[i][1];
            float v0 = (dot0 * dot0) / (qn4[i] + kna - 2.f * dot0 + 1e-6f);
            float v1 = (dot1 * dot1) / (qn4[i] + knb - 2.f * dot1 + 1e-6f);
            if (diag) {
                int row = qbase + i0 + i;
                if (k0 + j0 + 0 > row) v0 = -1e30f;
                if (k0 + j0 + 1 > row) v1 = -1e30f;
            }
            sc[i][0] = v0;
            sc[i][1] = v1;
        }

        // Online softmax: shuffle reductions, per-thread state
        float p[4][2], alpha[4];
#pragma unroll
        for (int i = 0; i < 4; i++) {
            float rmax = hw_max(fmaxf(sc[i][0], sc[i][1]));
            float mn = fmaxf(mreg[i], rmax);
            float al = __expf(mreg[i] - mn);
            mreg[i] = mn;
            alpha[i] = al;
            p[i][0] = __expf(sc[i][0] - mn);
            p[i][1] = __expf(sc[i][1] - mn);
            float ps = hw_sum(p[i][0] + p[i][1]);
            lreg[i] = lreg[i] * al + ps;
        }

        // Write P transposed
        {
            float4 c0 = make_float4(p[0][0], p[1][0], p[2][0], p[3][0]);
            float4 c1 = make_float4(p[0][1], p[1][1], p[2][1], p[3][1]);
            *(float4*)&Ps[j0 + 0][i0] = c0;
            *(float4*)&Ps[j0 + 1][i0] = c1;
        }
        __syncthreads();

        // Rescale O and accumulate PV
#pragma unroll
        for (int i = 0; i < 4; i++)
#pragma unroll
            for (int d = 0; d < 4; d++) o[i][d] *= alpha[i];

#pragma unroll 8
        for (int j = 0; j < BK; j++) {
            float4 pv = *(const float4*)&Ps[j][i0];
            float4 vv = *(const float4*)&Vs[j][d0];
            o[0][0] += pv.x * vv.x; o[0][1] += pv.x * vv.y;
            o[0][2] += pv.x * vv.z; o[0][3] += pv.x * vv.w;
            o[1][0] += pv.y * vv.x; o[1][1] += pv.y * vv.y;
            o[1][2] += pv.y * vv.z; o[1][3] += pv.y * vv.w;
            o[2][0] += pv.z * vv.x; o[2][1] += pv.z * vv.y;
            o[2][2] += pv.z * vv.z; o[2][3] += pv.z * vv.w;
            o[3][0] += pv.w * vv.x; o[3][1] += pv.w * vv.y;
            o[3][2] += pv.w * vv.z; o[3][3] += pv.w * vv.w;
        }
    }

    float* ob = g_att + (size_t)(b * L_SEQ + qbase) * EMB + h * HD;
#pragma unroll
    for (int i = 0; i < 4; i++) {
        float inv = 1.f / lreg[i];
        float4 r;
        r.x = o[i][0] * inv; r.y = o[i][1] * inv;
        r.z = o[i][2] * inv; r.w = o[i][3] * inv;
        *(float4*)(ob + (size_t)(i0 + i) * EMB + d0) = r;
    }
}

// ---------------------------------------------------------------------------
extern "C" void kernel_launch(void* const* d_in, const int* in_sizes, int n_in,
                              void* d_out, int out_size)
{
    const float* x     = (const float*)d_in[0];
    const float* w_qkv = (const float*)d_in[1];
    const float* b_qkv = (const float*)d_in[2];
    const float* w_out = (const float*)d_in[3];
    const float* b_out = (const float*)d_in[4];
    float* out = (float*)d_out;

    // 1) QKV projection (fp32 SGEMM, bias fused)
    {
        dim3 grid(QKV_N / 128, M_ROWS / 128);
        gemm_qkv_kernel<<<grid, 256>>>(x, w_qkv, b_qkv);
    }
    // 1b) q/k squared-norm precompute
    norm_kernel<<<(BATCH * NHEAD * L_SEQ) / 256, 256>>>();
    // 2) Yat causal attention (fp32, shuffle-reduced online softmax)
    {
        dim3 grid(L_SEQ / BQ, NHEAD, BATCH);
        yat_attn_kernel<<<grid, 256>>>();
    }
    // 3) Output projection (fp32 SGEMM, bias fused)
    {
        dim3 grid(EMB / 128, M_ROWS / 128);
        gemm_out_kernel<<<grid, 256>>>(w_out, b_out, out);
    }
}

// round 17
// speedup vs baseline: 1.6092x; 1.6092x over previous
#include <cuda_runtime.h>
#include <math.h>

#define L_SEQ   2048
#define EMB     1024
#define NHEAD   16
#define HD      64
#define BATCH   2
#define M_ROWS  (BATCH * L_SEQ)   /* 4096 */
#define QKV_N   (3 * EMB)         /* 3072 */

#define BQ 64
#define BK 32

// ---------------- Scratch (allocation-free) ----------------
__device__ float g_qkv[(size_t)M_ROWS * QKV_N];   // 48 MB
__device__ float g_att[(size_t)M_ROWS * EMB];     // 16 MB

// ---------------- packed fp32x2 helpers (Blackwell FFMA2) ------------------
typedef unsigned long long u64t;

__device__ __forceinline__ u64t pk2(float lo, float hi) {
    u64t r;
    asm("mov.b64 %0, {%1, %2};" : "=l"(r) : "r"(__float_as_uint(lo)), "r"(__float_as_uint(hi)));
    return r;
}
__device__ __forceinline__ void upk2(u64t v, float& lo, float& hi) {
    unsigned int a, b;
    asm("mov.b64 {%0, %1}, %2;" : "=r"(a), "=r"(b) : "l"(v));
    lo = __uint_as_float(a);
    hi = __uint_as_float(b);
}
__device__ __forceinline__ u64t fma2(u64t a, u64t b, u64t c) {
    u64t d;
    asm("fma.rn.f32x2 %0, %1, %2, %3;" : "=l"(d) : "l"(a), "l"(b), "l"(c));
    return d;
}

// ---------------------------------------------------------------------------
// fp32 SGEMM with packed f32x2 inner product: C = A@B + bias
// Structure identical to the proven R4 kernel (128x128 tile, K-step 8,
// 256 threads, 8x8 microtile, double-buffered smem); only the accumulate
// uses fma.rn.f32x2 (32 packed FMA per kk instead of 64 scalar FFMA).
// ---------------------------------------------------------------------------
__device__ __forceinline__ void sgemm_body(const float* __restrict__ A,
                                           const float* __restrict__ B,
                                           const float* __restrict__ bias,
                                           float* __restrict__ C,
                                           int M, int N, int K)
{
    __shared__ __align__(16) float As[2][8][132];   // [buf][k][m] transposed
    __shared__ __align__(16) float Bs[2][8][132];   // [buf][k][n]

    const int tid = threadIdx.x;
    const int bm = blockIdx.y * 128;
    const int bn = blockIdx.x * 128;

    const int tx = tid % 16;
    const int ty = tid / 16;

    const int arow  = tid >> 1;
    const int acol4 = (tid & 1) * 4;
    const int brow = tid >> 5;
    const int bcol = (tid & 31) * 4;

    u64t acc2[8][4];
#pragma unroll
    for (int i = 0; i < 8; i++)
#pragma unroll
        for (int jp = 0; jp < 4; jp++) acc2[i][jp] = 0ull;   // (0.f, 0.f)

    float4 a4 = *(const float4*)(A + (size_t)(bm + arow) * K + acol4);
    float4 b4 = *(const float4*)(B + (size_t)brow * N + bn + bcol);
    As[0][acol4 + 0][arow] = a4.x;
    As[0][acol4 + 1][arow] = a4.y;
    As[0][acol4 + 2][arow] = a4.z;
    As[0][acol4 + 3][arow] = a4.w;
    *(float4*)&Bs[0][brow][bcol] = b4;
    __syncthreads();

    int cur = 0;
    for (int k0 = 0; k0 < K; k0 += 8) {
        const int nxt = cur ^ 1;
        const bool more = (k0 + 8 < K);
        if (more) {
            a4 = *(const float4*)(A + (size_t)(bm + arow) * K + k0 + 8 + acol4);
            b4 = *(const float4*)(B + (size_t)(k0 + 8 + brow) * N + bn + bcol);
        }

#pragma unroll
        for (int kk = 0; kk < 8; kk++) {
            float a[8];
#pragma unroll
            for (int h4 = 0; h4 < 2; h4++) {
                float4 t = *(const float4*)&As[cur][kk][ty * 8 + h4 * 4];
                a[h4*4+0]=t.x; a[h4*4+1]=t.y; a[h4*4+2]=t.z; a[h4*4+3]=t.w;
            }
            // B pairs loaded directly as packed f32x2 operands
            ulonglong2 bu0 = *(const ulonglong2*)&Bs[cur][kk][tx * 8];
            ulonglong2 bu1 = *(const ulonglong2*)&Bs[cur][kk][tx * 8 + 4];
            u64t b2[4] = {bu0.x, bu0.y, bu1.x, bu1.y};
#pragma unroll
            for (int i = 0; i < 8; i++) {
                u64t a2 = pk2(a[i], a[i]);
#pragma unroll
                for (int jp = 0; jp < 4; jp++)
                    acc2[i][jp] = fma2(a2, b2[jp], acc2[i][jp]);
            }
        }

        if (more) {
            As[nxt][acol4 + 0][arow] = a4.x;
            As[nxt][acol4 + 1][arow] = a4.y;
            As[nxt][acol4 + 2][arow] = a4.z;
            As[nxt][acol4 + 3][arow] = a4.w;
            *(float4*)&Bs[nxt][brow][bcol] = b4;
        }
        __syncthreads();
        cur = nxt;
    }

#pragma unroll
    for (int i = 0; i < 8; i++) {
        int m = bm + ty * 8 + i;
        float c8[8];
#pragma unroll
        for (int jp = 0; jp < 4; jp++)
            upk2(acc2[i][jp], c8[2*jp], c8[2*jp+1]);
#pragma unroll
        for (int j = 0; j < 8; j += 4) {
            int n = bn + tx * 8 + j;
            float4 r;
            r.x = c8[j + 0] + bias[n + 0];
            r.y = c8[j + 1] + bias[n + 1];
            r.z = c8[j + 2] + bias[n + 2];
            r.w = c8[j + 3] + bias[n + 3];
            *(float4*)(C + (size_t)m * N + n) = r;
        }
    }
}

__global__ __launch_bounds__(256, 2) void gemm_qkv_kernel(const float* __restrict__ x,
                                                          const float* __restrict__ w,
                                                          const float* __restrict__ bias)
{
    sgemm_body(x, w, bias, g_qkv, M_ROWS, QKV_N, EMB);
}

__global__ __launch_bounds__(256, 2) void gemm_out_kernel(const float* __restrict__ w,
                                                          const float* __restrict__ bias,
                                                          float* __restrict__ out)
{
    sgemm_body(g_att, w, bias, out, M_ROWS, EMB, EMB);
}

// ---------------------------------------------------------------------------
// Yat causal attention — byte-identical to the PASSING R4 kernel (scalar fp32).
// ---------------------------------------------------------------------------
__global__ __launch_bounds__(256) void yat_attn_kernel()
{
    __shared__ __align__(16) float Qs[BQ][68];
    __shared__ __align__(16) float Ks[BK][68];
    __shared__ __align__(16) float Vs[BK][68];
    __shared__ __align__(16) float Ps[BK][68];   // P transposed: Ps[j][i]
    __shared__ float red[BQ][17];
    __shared__ float qn[BQ], mrow[BQ], lrow[BQ], arow[BQ];
    __shared__ float kn[BK];

    const int qt = blockIdx.x;
    const int h  = blockIdx.y;
    const int b  = blockIdx.z;
    const int tid = threadIdx.x;
    const int tx = tid & 15;
    const int ty = tid >> 4;
    const int i0 = ty * 4;
    const int j0 = tx * 2;
    const int d0 = tx * 4;
    const int qbase = qt * BQ;

    const float* qkv_b = g_qkv + (size_t)b * L_SEQ * QKV_N;

    for (int it = tid; it < BQ * 16; it += 256) {
        int r = it >> 4, c4 = (it & 15) * 4;
        *(float4*)&Qs[r][c4] =
            *(const float4*)(qkv_b + (size_t)(qbase + r) * QKV_N + h * HD + c4);
    }
    __syncthreads();
    if (tid < BQ) {
        float s = 0.f;
#pragma unroll
        for (int d = 0; d < HD; d++) s += Qs[tid][d] * Qs[tid][d];
        qn[tid] = s;
        mrow[tid] = -1e30f;
        lrow[tid] = 0.f;
    }

    float o[4][4];
#pragma unroll
    for (int i = 0; i < 4; i++)
#pragma unroll
        for (int d = 0; d < 4; d++) o[i][d] = 0.f;

    const int nkt = 2 * qt + 2;
    for (int kt = 0; kt < nkt; kt++) {
        const int k0 = kt * BK;
        const bool diag = (kt >= 2 * qt);
        __syncthreads();

        for (int it = tid; it < BK * 16; it += 256) {
            int r = it >> 4, c4 = (it & 15) * 4;
            const float* kp = qkv_b + (size_t)(k0 + r) * QKV_N + EMB + h * HD + c4;
            *(float4*)&Ks[r][c4] = *(const float4*)kp;
            *(float4*)&Vs[r][c4] = *(const float4*)(kp + EMB);
        }
        __syncthreads();
        if (tid < BK) {
            float s = 0.f;
#pragma unroll
            for (int d = 0; d < HD; d++) s += Ks[tid][d] * Ks[tid][d];
            kn[tid] = s;
        }
        __syncthreads();

        float s_[4][2];
#pragma unroll
        for (int i = 0; i < 4; i++) { s_[i][0] = 0.f; s_[i][1] = 0.f; }
#pragma unroll
        for (int d = 0; d < HD; d += 4) {
            float4 k0v = *(const float4*)&Ks[j0 + 0][d];
            float4 k1v = *(const float4*)&Ks[j0 + 1][d];
#pragma unroll
            for (int i = 0; i < 4; i++) {
                float4 qv = *(const float4*)&Qs[i0 + i][d];
                s_[i][0] += qv.x * k0v.x + qv.y * k0v.y + qv.z * k0v.z + qv.w * k0v.w;
                s_[i][1] += qv.x * k1v.x + qv.y * k1v.y + qv.z * k1v.z + qv.w * k1v.w;
            }
        }

        float sc[4][2];
#pragma unroll
        for (int i = 0; i < 4; i++) {
            float qni = qn[i0 + i];
#pragma unroll
            for (int j = 0; j < 2; j++) {
                float dot = s_[i][j];
                float denom = qni + kn[j0 + j] - 2.f * dot + 1e-6f;
                float v = (dot * dot) / denom;
                if (diag && (k0 + j0 + j > qbase + i0 + i)) v = -1e30f;
                sc[i][j] = v;
            }
        }

#pragma unroll
        for (int i = 0; i < 4; i++)
            red[i0 + i][tx] = fmaxf(sc[i][0], sc[i][1]);
        __syncthreads();
        if (tid < BQ) {
            float mx = red[tid][0];
#pragma unroll
            for (int t = 1; t < 16; t++) mx = fmaxf(mx, red[tid][t]);
            float mo = mrow[tid];
            float mn = fmaxf(mo, mx);
            float al = __expf(mo - mn);
            mrow[tid] = mn;
            arow[tid] = al;
            lrow[tid] *= al;
        }
        __syncthreads();

        float p[4][2];
        float psum[4];
#pragma unroll
        for (int i = 0; i < 4; i++) {
            float mi = mrow[i0 + i];
            p[i][0] = __expf(sc[i][0] - mi);
            p[i][1] = __expf(sc[i][1] - mi);
            psum[i] = p[i][0] + p[i][1];
        }
        {
            float4 c0 = make_float4(p[0][0], p[1][0], p[2][0], p[3][0]);
            float4 c1 = make_float4(p[0][1], p[1][1], p[2][1], p[3][1]);
            *(float4*)&Ps[j0 + 0][i0] = c0;
            *(float4*)&Ps[j0 + 1][i0] = c1;
        }
#pragma unroll
        for (int i = 0; i < 4; i++)
            red[i0 + i][tx] = psum[i];
        __syncthreads();
        if (tid < BQ) {
            float s = red[tid][0];
#pragma unroll
            for (int t = 1; t < 16; t++) s += red[tid][t];
            lrow[tid] += s;
        }

        float a_[4];
#pragma unroll
        for (int i = 0; i < 4; i++) a_[i] = arow[i0 + i];
#pragma unroll
        for (int i = 0; i < 4; i++)
#pragma unroll
            for (int d = 0; d < 4; d++) o[i][d] *= a_[i];

#pragma unroll 8
        for (int j = 0; j < BK; j++) {
            float4 pv = *(const float4*)&Ps[j][i0];
            float4 vv = *(const float4*)&Vs[j][d0];
            o[0][0] += pv.x * vv.x; o[0][1] += pv.x * vv.y;
            o[0][2] += pv.x * vv.z; o[0][3] += pv.x * vv.w;
            o[1][0] += pv.y * vv.x; o[1][1] += pv.y * vv.y;
            o[1][2] += pv.y * vv.z; o[1][3] += pv.y * vv.w;
            o[2][0] += pv.z * vv.x; o[2][1] += pv.z * vv.y;
            o[2][2] += pv.z * vv.z; o[2][3] += pv.z * vv.w;
            o[3][0] += pv.w * vv.x; o[3][1] += pv.w * vv.y;
            o[3][2] += pv.w * vv.z; o[3][3] += pv.w * vv.w;
        }
    }
    __syncthreads();

    float* ob = g_att + (size_t)(b * L_SEQ + qbase) * EMB + h * HD;
#pragma unroll
    for (int i = 0; i < 4; i++) {
        float inv = 1.f / lrow[i0 + i];
        float4 r;
        r.x = o[i][0] * inv; r.y = o[i][1] * inv;
        r.z = o[i][2] * inv; r.w = o[i][3] * inv;
        *(float4*)(ob + (size_t)(i0 + i) * EMB + d0) = r;
    }
}

// ---------------------------------------------------------------------------
extern "C" void kernel_launch(void* const* d_in, const int* in_sizes, int n_in,
                              void* d_out, int out_size)
{
    const float* x     = (const float*)d_in[0];
    const float* w_qkv = (const float*)d_in[1];
    const float* b_qkv = (const float*)d_in[2];
    const float* w_out = (const float*)d_in[3];
    const float* b_out = (const float*)d_in[4];
    float* out = (float*)d_out;

    // 1) QKV projection: [4096,1024] @ [1024,3072]
    {
        dim3 grid(QKV_N / 128, M_ROWS / 128);
        gemm_qkv_kernel<<<grid, 256>>>(x, w_qkv, b_qkv);
    }
    // 2) Yat causal attention
    {
        dim3 grid(L_SEQ / BQ, NHEAD, BATCH);
        yat_attn_kernel<<<grid, 256>>>();
    }
    // 3) Output projection: [4096,1024] @ [1024,1024]
    {
        dim3 grid(EMB / 128, M_ROWS / 128);
        gemm_out_kernel<<<grid, 256>>>(w_out, b_out, out);
    }
}